// round 1
// baseline (speedup 1.0000x reference)
#include <cuda_runtime.h>
#include <math.h>

#define KCODES 1024
#define DDIM   64

// -------- scratch (device globals; no allocation allowed) --------
__device__ float g_en2[KCODES];
__device__ float g_nrm[KCODES * DDIM];
__device__ int   g_hist[KCODES];
__device__ int   g_used;
__device__ float g_pcommit[1024];
__device__ float g_pent[1024];
__device__ float g_portho[DDIM];

// -------- zero per-launch state --------
__global__ void zero_kernel() {
    int i = blockIdx.x * blockDim.x + threadIdx.x;
    if (i < KCODES) g_hist[i] = 0;
    if (i == 0) g_used = 0;
}

// -------- codebook prep: ||e||^2, normalized+masked rows, used count --------
__global__ void prep_kernel(const float* __restrict__ emb, const float* __restrict__ cc) {
    int row = blockIdx.x * blockDim.x + threadIdx.x;
    if (row >= KCODES) return;
    const float4* e4 = ((const float4*)emb) + (size_t)row * (DDIM / 4);
    float4 v[16];
    float s = 0.f;
#pragma unroll
    for (int i = 0; i < 16; i++) {
        v[i] = e4[i];
        s += v[i].x * v[i].x + v[i].y * v[i].y + v[i].z * v[i].z + v[i].w * v[i].w;
    }
    g_en2[row] = s;
    float nr = sqrtf(s);
    nr = fmaxf(nr, 1e-12f);
    float msk = (cc[row] >= 1.f) ? 1.f : 0.f;
    if (msk != 0.f) atomicAdd(&g_used, 1);
    float sc = msk / nr;
    float4* o4 = ((float4*)g_nrm) + (size_t)row * (DDIM / 4);
#pragma unroll
    for (int i = 0; i < 16; i++) {
        float4 t = v[i];
        t.x *= sc; t.y *= sc; t.z *= sc; t.w *= sc;
        o4[i] = t;
    }
}

// -------- shared memory layout (floats) --------
// Xs: [64][132]  (D-major, padded)            offset 0      size 8448
// Es: [64][132]                                offset 8448   size 8448
// en2s: [128]                                  offset 16896  size 128
// Rm/Rz/Rs: [128][16]                          17024/19072/21120 (2048 each)
// Ri: int [128][16]                            23168 (2048)
// idxRow: int [128]                            25216 (128)
// scr: [256]                                   25344 (256)
// total 25600 floats = 102400 bytes
#define SMEM_FLOATS 25600
#define SMEM_BYTES  (SMEM_FLOATS * 4)

__global__ __launch_bounds__(256, 1)
void main_kernel(const float* __restrict__ x, const float* __restrict__ emb,
                 float* __restrict__ qout, float* __restrict__ idxout) {
    extern __shared__ float sm[];
    float* Xs   = sm;
    float* Es   = sm + 8448;
    float* en2s = sm + 16896;
    float* Rm   = sm + 17024;
    float* Rz   = sm + 19072;
    float* Rs   = sm + 21120;
    int*   Ri   = (int*)(sm + 23168);
    int*   idxRow = (int*)(sm + 25216);
    float* scr  = sm + 25344;

    const int tid = threadIdx.x;
    const int tx = tid & 15;   // code group
    const int ty = tid >> 4;   // row group
    const int r0 = blockIdx.x * 128;

    // load X tile transposed: Xs[d][row]
#pragma unroll
    for (int i = 0; i < 8; i++) {
        int v = tid + 256 * i;          // 2048 float4s
        int row = v >> 4;
        int c4 = v & 15;
        float4 t = ((const float4*)x)[(size_t)(r0 + row) * 16 + c4];
        int d = c4 * 4;
        Xs[(d + 0) * 132 + row] = t.x;
        Xs[(d + 1) * 132 + row] = t.y;
        Xs[(d + 2) * 132 + row] = t.z;
        Xs[(d + 3) * 132 + row] = t.w;
    }

    float m[8], Z[8], S[8];
    int   bi[8];
#pragma unroll
    for (int i = 0; i < 8; i++) { m[i] = -1e30f; Z[i] = 0.f; S[i] = 0.f; bi[i] = 0; }

    for (int t = 0; t < 8; t++) {
        __syncthreads();
        // load E tile transposed: Es[d][code]
#pragma unroll
        for (int i = 0; i < 8; i++) {
            int v = tid + 256 * i;
            int code = v >> 4;
            int c4 = v & 15;
            float4 tv = ((const float4*)emb)[(size_t)(t * 128 + code) * 16 + c4];
            int d = c4 * 4;
            Es[(d + 0) * 132 + code] = tv.x;
            Es[(d + 1) * 132 + code] = tv.y;
            Es[(d + 2) * 132 + code] = tv.z;
            Es[(d + 3) * 132 + code] = tv.w;
        }
        if (tid < 128) en2s[tid] = g_en2[t * 128 + tid];
        __syncthreads();

        float acc[8][8];
#pragma unroll
        for (int i = 0; i < 8; i++)
#pragma unroll
            for (int j = 0; j < 8; j++) acc[i][j] = 0.f;

#pragma unroll 8
        for (int kk = 0; kk < 64; kk++) {
            float a[8], b[8];
            float4 a0 = *(const float4*)(Xs + kk * 132 + ty * 8);
            float4 a1 = *(const float4*)(Xs + kk * 132 + ty * 8 + 4);
            float4 b0 = *(const float4*)(Es + kk * 132 + tx * 8);
            float4 b1 = *(const float4*)(Es + kk * 132 + tx * 8 + 4);
            a[0] = a0.x; a[1] = a0.y; a[2] = a0.z; a[3] = a0.w;
            a[4] = a1.x; a[5] = a1.y; a[6] = a1.z; a[7] = a1.w;
            b[0] = b0.x; b[1] = b0.y; b[2] = b0.z; b[3] = b0.w;
            b[4] = b1.x; b[5] = b1.y; b[6] = b1.z; b[7] = b1.w;
#pragma unroll
            for (int i = 0; i < 8; i++)
#pragma unroll
                for (int j = 0; j < 8; j++)
                    acc[i][j] = fmaf(a[i], b[j], acc[i][j]);
        }

        // fused epilogue: a' = 2*dot - ||e||^2 (softmax/argmin invariant to ||x||^2)
#pragma unroll
        for (int j = 0; j < 8; j++) {
            float e2 = en2s[tx * 8 + j];
            int jg = t * 128 + tx * 8 + j;
#pragma unroll
            for (int i = 0; i < 8; i++) {
                float av = fmaf(2.f, acc[i][j], -e2);
                if (av > m[i]) {
                    float scl = __expf(m[i] - av);
                    Z[i] = fmaf(Z[i], scl, 1.f);
                    S[i] = fmaf(S[i], scl, av);
                    m[i] = av;
                    bi[i] = jg;
                } else {
                    float p = __expf(av - m[i]);
                    Z[i] += p;
                    S[i] = fmaf(av, p, S[i]);
                }
            }
        }
    }

    __syncthreads();
#pragma unroll
    for (int i = 0; i < 8; i++) {
        int row = ty * 8 + i;
        Rm[row * 16 + tx] = m[i];
        Rz[row * 16 + tx] = Z[i];
        Rs[row * 16 + tx] = S[i];
        Ri[row * 16 + tx] = bi[i];
    }
    __syncthreads();

    float H = 0.f;
    if (tid < 128) {
        int row = tid;
        float mm = -1e30f;
        int ii = 0x7fffffff;
#pragma unroll
        for (int t2 = 0; t2 < 16; t2++) {
            float mv = Rm[row * 16 + t2];
            int iv = Ri[row * 16 + t2];
            if (mv > mm) { mm = mv; ii = iv; }
            else if (mv == mm && iv < ii) ii = iv;
        }
        float zz = 0.f, ss = 0.f;
#pragma unroll
        for (int t2 = 0; t2 < 16; t2++) {
            float scl = __expf(Rm[row * 16 + t2] - mm);
            zz = fmaf(Rz[row * 16 + t2], scl, zz);
            ss = fmaf(Rs[row * 16 + t2], scl, ss);
        }
        // H = log(sum e^a) - E[a]  (invariant to per-row constant)
        H = mm + __logf(zz) - ss / zz;
        idxRow[row] = ii;
        idxout[r0 + row] = (float)ii;
        atomicAdd(&g_hist[ii], 1);
    }
    scr[tid] = (tid < 128) ? H : 0.f;
    __syncthreads();
    for (int s = 128; s > 0; s >>= 1) {
        if (tid < s) scr[tid] += scr[tid + s];
        __syncthreads();
    }
    if (tid == 0) g_pent[blockIdx.x] = scr[0];
    __syncthreads();

    // gather quantized rows, write output, accumulate commitment
    float ca = 0.f;
#pragma unroll
    for (int i = 0; i < 8; i++) {
        int v = tid + 256 * i;
        int row = v >> 4;
        int c4 = v & 15;
        int code = idxRow[row];
        float4 q = ((const float4*)emb)[(size_t)code * 16 + c4];
        float4 xv = ((const float4*)x)[(size_t)(r0 + row) * 16 + c4];
        ((float4*)qout)[(size_t)(r0 + row) * 16 + c4] = q;
        float dx = q.x - xv.x, dy = q.y - xv.y, dz = q.z - xv.z, dw = q.w - xv.w;
        ca += dx * dx + dy * dy + dz * dz + dw * dw;
    }
    scr[tid] = ca;
    __syncthreads();
    for (int s = 128; s > 0; s >>= 1) {
        if (tid < s) scr[tid] += scr[tid + s];
        __syncthreads();
    }
    if (tid == 0) g_pcommit[blockIdx.x] = scr[0];
}

// -------- ortho loss via Gram trick: sum(cos^2) = ||N^T N||_F^2, N^T N is 64x64 --------
__global__ void ortho_kernel() {
    int a = blockIdx.x;    // 0..63
    int b = threadIdx.x;   // 0..63
    float acc = 0.f;
#pragma unroll 4
    for (int k = 0; k < KCODES; k++)
        acc = fmaf(g_nrm[k * DDIM + a], g_nrm[k * DDIM + b], acc);
    __shared__ float sh[64];
    sh[b] = acc * acc;
    __syncthreads();
    for (int s = 32; s > 0; s >>= 1) {
        if (b < s) sh[b] += sh[b + s];
        __syncthreads();
    }
    if (b == 0) g_portho[a] = sh[0];
}

// -------- finalize scalars --------
__global__ void fin_kernel(float* __restrict__ out, int N, int nblocks) {
    __shared__ float sh[256];
    int tid = threadIdx.x;

    float v = 0.f;
    for (int i = tid; i < nblocks; i += 256) v += g_pcommit[i];
    sh[tid] = v;
    __syncthreads();
    for (int s = 128; s > 0; s >>= 1) { if (tid < s) sh[tid] += sh[tid + s]; __syncthreads(); }
    float commitSum = sh[0];
    __syncthreads();

    v = 0.f;
    for (int i = tid; i < nblocks; i += 256) v += g_pent[i];
    sh[tid] = v;
    __syncthreads();
    for (int s = 128; s > 0; s >>= 1) { if (tid < s) sh[tid] += sh[tid + s]; __syncthreads(); }
    float entSum = sh[0];
    __syncthreads();

    sh[tid] = (tid < DDIM) ? g_portho[tid] : 0.f;
    __syncthreads();
    for (int s = 128; s > 0; s >>= 1) { if (tid < s) sh[tid] += sh[tid + s]; __syncthreads(); }
    float orthoSum = sh[0];
    __syncthreads();

    v = 0.f;
    for (int i = tid; i < KCODES; i += 256) {
        float avg = (float)g_hist[i] / (float)N;
        v += avg * logf(avg + 1e-10f);
    }
    sh[tid] = v;
    __syncthreads();
    for (int s = 128; s > 0; s >>= 1) { if (tid < s) sh[tid] += sh[tid + s]; __syncthreads(); }
    float psum = sh[0];

    if (tid == 0) {
        size_t Q = (size_t)N * DDIM;
        float nu = (float)g_used;
        out[Q + 0] = commitSum / (float)Q;                      // commitment_loss
        out[Q + 1] = orthoSum / (nu * nu) - 1.f / nu;           // ortho_loss
        out[Q + 2] = entSum / ((float)N * 10.f);                // entropy_loss (/log2(1024))
        out[Q + 3] = expf(-psum);                               // perplexity
        out[Q + 4] = nu / (float)KCODES;                        // coverage
    }
}

extern "C" void kernel_launch(void* const* d_in, const int* in_sizes, int n_in,
                              void* d_out, int out_size) {
    const float* x   = (const float*)d_in[0];   // [16,2048,64] fp32
    const float* emb = (const float*)d_in[1];   // [1024,64] fp32
    const float* cc  = (const float*)d_in[2];   // [1024] fp32
    int N = in_sizes[0] / DDIM;                 // 32768 rows
    int nblocks = N / 128;

    float* out = (float*)d_out;
    float* qout = out;                                  // [N*64]
    float* idxout = out + (size_t)N * DDIM + 5;         // [N] after 5 scalars

    cudaFuncSetAttribute(main_kernel, cudaFuncAttributeMaxDynamicSharedMemorySize, SMEM_BYTES);

    zero_kernel<<<4, 256>>>();
    prep_kernel<<<4, 256>>>(emb, cc);
    main_kernel<<<nblocks, 256, SMEM_BYTES>>>(x, emb, qout, idxout);
    ortho_kernel<<<DDIM, DDIM>>>();
    fin_kernel<<<1, 256>>>(out, N, nblocks);
}

// round 3
// speedup vs baseline: 1.2426x; 1.2426x over previous
#include <cuda_runtime.h>
#include <math.h>

#define KCODES 1024
#define DDIM   64

// -------- scratch (device globals; no allocation allowed) --------
__device__ float g_en2[KCODES];
__device__ float g_nrm[KCODES * DDIM];
__device__ int   g_hist[KCODES];
__device__ float g_usedp[4];
__device__ float g_pcommit[256];
__device__ float g_pent[256];
__device__ float g_gramp[16 * 4096];

// -------- packed f32x2 helpers (sm_103a FFMA2) --------
struct __align__(16) ULL2 { unsigned long long x, y; };

__device__ __forceinline__ unsigned long long pack2(float a, float b) {
    unsigned long long r;
    asm("mov.b64 %0, {%1,%2};" : "=l"(r) : "f"(a), "f"(b));
    return r;
}
__device__ __forceinline__ void unpack2(unsigned long long v, float& lo, float& hi) {
    asm("mov.b64 {%0,%1}, %2;" : "=f"(lo), "=f"(hi) : "l"(v));
}
#define FMA2(d, a, b) asm("fma.rn.f32x2 %0, %1, %2, %0;" : "+l"(d) : "l"(a), "l"(b))

// -------- codebook prep: ||e||^2, normalized+masked rows, hist zero, used partials --------
__global__ void prep_kernel(const float* __restrict__ emb, const float* __restrict__ cc) {
    int row = blockIdx.x * blockDim.x + threadIdx.x;
    const float4* e4 = ((const float4*)emb) + (size_t)row * (DDIM / 4);
    float4 v[16];
    float s = 0.f;
#pragma unroll
    for (int i = 0; i < 16; i++) {
        v[i] = e4[i];
        s += v[i].x * v[i].x + v[i].y * v[i].y + v[i].z * v[i].z + v[i].w * v[i].w;
    }
    g_en2[row] = s;
    g_hist[row] = 0;
    float nr = fmaxf(sqrtf(s), 1e-12f);
    float msk = (cc[row] >= 1.f) ? 1.f : 0.f;
    float sc = msk / nr;
    float4* o4 = ((float4*)g_nrm) + (size_t)row * (DDIM / 4);
#pragma unroll
    for (int i = 0; i < 16; i++) {
        float4 t = v[i];
        t.x *= sc; t.y *= sc; t.z *= sc; t.w *= sc;
        o4[i] = t;
    }
    __shared__ float sh[256];
    sh[threadIdx.x] = msk;
    __syncthreads();
    for (int st = 128; st > 0; st >>= 1) {
        if (threadIdx.x < st) sh[threadIdx.x] += sh[threadIdx.x + st];
        __syncthreads();
    }
    if (threadIdx.x == 0) g_usedp[blockIdx.x] = sh[0];
}

// -------- ortho partial Gram: block b handles codes [b*64, b*64+64) --------
__global__ __launch_bounds__(256, 4)
void ortho_kernel() {
    __shared__ float nt[64 * 68];
    int tid = threadIdx.x;
    int k0 = blockIdx.x * 64;
#pragma unroll
    for (int i = 0; i < 16; i++) {
        int v = tid + 256 * i;
        int k = v >> 6, d = v & 63;
        nt[k * 68 + d] = g_nrm[(size_t)(k0 + k) * DDIM + d];
    }
    __syncthreads();
    int a = tid >> 2;          // 0..63
    int bg = tid & 3;          // 0..3 -> cols bg*16..+15
    float acc[16];
#pragma unroll
    for (int i = 0; i < 16; i++) acc[i] = 0.f;
#pragma unroll 4
    for (int k = 0; k < 64; k++) {
        float va = nt[k * 68 + a];
        const float4* bp = (const float4*)(nt + k * 68 + bg * 16);
        float4 q0 = bp[0], q1 = bp[1], q2 = bp[2], q3 = bp[3];
        acc[0]  = fmaf(va, q0.x, acc[0]);  acc[1]  = fmaf(va, q0.y, acc[1]);
        acc[2]  = fmaf(va, q0.z, acc[2]);  acc[3]  = fmaf(va, q0.w, acc[3]);
        acc[4]  = fmaf(va, q1.x, acc[4]);  acc[5]  = fmaf(va, q1.y, acc[5]);
        acc[6]  = fmaf(va, q1.z, acc[6]);  acc[7]  = fmaf(va, q1.w, acc[7]);
        acc[8]  = fmaf(va, q2.x, acc[8]);  acc[9]  = fmaf(va, q2.y, acc[9]);
        acc[10] = fmaf(va, q2.z, acc[10]); acc[11] = fmaf(va, q2.w, acc[11]);
        acc[12] = fmaf(va, q3.x, acc[12]); acc[13] = fmaf(va, q3.y, acc[13]);
        acc[14] = fmaf(va, q3.z, acc[14]); acc[15] = fmaf(va, q3.w, acc[15]);
    }
    float4* op = (float4*)(g_gramp + (size_t)blockIdx.x * 4096 + a * 64 + bg * 16);
#pragma unroll
    for (int i = 0; i < 4; i++)
        op[i] = make_float4(acc[i * 4], acc[i * 4 + 1], acc[i * 4 + 2], acc[i * 4 + 3]);
}

// -------- shared memory layout (floats), total 25600 floats = 102400 bytes --------
#define SMEM_FLOATS 25600
#define SMEM_BYTES  (SMEM_FLOATS * 4)

__global__ __launch_bounds__(256, 1)
void main_kernel(const float* __restrict__ x, const float* __restrict__ emb,
                 float* __restrict__ qout, float* __restrict__ idxout) {
    extern __shared__ float sm[];
    float* Xs   = sm;               // [64][132]
    float* Es   = sm + 8448;        // [64][132]
    float* en2s = sm + 16896;       // [128]
    float* Rm   = sm + 17024;       // [128][16]
    float* Rz   = sm + 19072;
    float* Rs   = sm + 21120;
    int*   Ri   = (int*)(sm + 23168);
    int*   idxRow = (int*)(sm + 25216);
    float* scr  = sm + 25344;       // [256]

    const int tid = threadIdx.x;
    const int tx = tid & 15;   // code group
    const int ty = tid >> 4;   // row group
    const int r0 = blockIdx.x * 128;

    // load X tile transposed: Xs[d][row]
#pragma unroll
    for (int i = 0; i < 8; i++) {
        int v = tid + 256 * i;
        int row = v >> 4;
        int c4 = v & 15;
        float4 t = ((const float4*)x)[(size_t)(r0 + row) * 16 + c4];
        int d = c4 * 4;
        Xs[(d + 0) * 132 + row] = t.x;
        Xs[(d + 1) * 132 + row] = t.y;
        Xs[(d + 2) * 132 + row] = t.z;
        Xs[(d + 3) * 132 + row] = t.w;
    }

    float m[8], Z[8], S[8];
    int   bi[8];
#pragma unroll
    for (int i = 0; i < 8; i++) { m[i] = -1e30f; Z[i] = 0.f; S[i] = 0.f; bi[i] = 0; }

    const unsigned long long zero2 = pack2(0.f, 0.f);

    for (int t = 0; t < 8; t++) {
        __syncthreads();
        // load E tile transposed: Es[d][code]
#pragma unroll
        for (int i = 0; i < 8; i++) {
            int v = tid + 256 * i;
            int code = v >> 4;
            int c4 = v & 15;
            float4 tv = ((const float4*)emb)[(size_t)(t * 128 + code) * 16 + c4];
            int d = c4 * 4;
            Es[(d + 0) * 132 + code] = tv.x;
            Es[(d + 1) * 132 + code] = tv.y;
            Es[(d + 2) * 132 + code] = tv.z;
            Es[(d + 3) * 132 + code] = tv.w;
        }
        if (tid < 128) en2s[tid] = g_en2[t * 128 + tid];
        __syncthreads();

        // packed accumulators: acc2[ip][j] holds rows (2ip, 2ip+1), col j
        unsigned long long acc2[4][8];
#pragma unroll
        for (int ip = 0; ip < 4; ip++)
#pragma unroll
            for (int j = 0; j < 8; j++) acc2[ip][j] = zero2;

#pragma unroll 8
        for (int kk = 0; kk < 64; kk++) {
            // A row-pairs come straight from the 128-bit smem loads (b64 view)
            ULL2 A0 = *(const ULL2*)(Xs + kk * 132 + ty * 8);
            ULL2 A1 = *(const ULL2*)(Xs + kk * 132 + ty * 8 + 4);
            unsigned long long aa[4] = { A0.x, A0.y, A1.x, A1.y };
            float4 b0 = *(const float4*)(Es + kk * 132 + tx * 8);
            float4 b1 = *(const float4*)(Es + kk * 132 + tx * 8 + 4);
            unsigned long long bb[8];
            bb[0] = pack2(b0.x, b0.x); bb[1] = pack2(b0.y, b0.y);
            bb[2] = pack2(b0.z, b0.z); bb[3] = pack2(b0.w, b0.w);
            bb[4] = pack2(b1.x, b1.x); bb[5] = pack2(b1.y, b1.y);
            bb[6] = pack2(b1.z, b1.z); bb[7] = pack2(b1.w, b1.w);
#pragma unroll
            for (int ip = 0; ip < 4; ip++)
#pragma unroll
                for (int j = 0; j < 8; j++)
                    FMA2(acc2[ip][j], aa[ip], bb[j]);
        }

        // fused epilogue: a' = 2*dot - ||e||^2 (softmax/argmin invariant to ||x||^2)
#pragma unroll
        for (int j = 0; j < 8; j++) {
            float e2 = en2s[tx * 8 + j];
            int jg = t * 128 + tx * 8 + j;
#pragma unroll
            for (int ip = 0; ip < 4; ip++) {
                float d0, d1;
                unpack2(acc2[ip][j], d0, d1);
                int i0 = 2 * ip, i1 = 2 * ip + 1;
                float av0 = fmaf(2.f, d0, -e2);
                if (av0 > m[i0]) {
                    float scl = __expf(m[i0] - av0);
                    Z[i0] = fmaf(Z[i0], scl, 1.f);
                    S[i0] = fmaf(S[i0], scl, av0);
                    m[i0] = av0; bi[i0] = jg;
                } else {
                    float p = __expf(av0 - m[i0]);
                    Z[i0] += p;
                    S[i0] = fmaf(av0, p, S[i0]);
                }
                float av1 = fmaf(2.f, d1, -e2);
                if (av1 > m[i1]) {
                    float scl = __expf(m[i1] - av1);
                    Z[i1] = fmaf(Z[i1], scl, 1.f);
                    S[i1] = fmaf(S[i1], scl, av1);
                    m[i1] = av1; bi[i1] = jg;
                } else {
                    float p = __expf(av1 - m[i1]);
                    Z[i1] += p;
                    S[i1] = fmaf(av1, p, S[i1]);
                }
            }
        }
    }

    __syncthreads();
#pragma unroll
    for (int i = 0; i < 8; i++) {
        int row = ty * 8 + i;
        Rm[row * 16 + tx] = m[i];
        Rz[row * 16 + tx] = Z[i];
        Rs[row * 16 + tx] = S[i];
        Ri[row * 16 + tx] = bi[i];
    }
    __syncthreads();

    float H = 0.f;
    if (tid < 128) {
        int row = tid;
        float mm = -1e30f;
        int ii = 0x7fffffff;
#pragma unroll
        for (int t2 = 0; t2 < 16; t2++) {
            float mv = Rm[row * 16 + t2];
            int iv = Ri[row * 16 + t2];
            if (mv > mm) { mm = mv; ii = iv; }
            else if (mv == mm && iv < ii) ii = iv;
        }
        float zz = 0.f, ss = 0.f;
#pragma unroll
        for (int t2 = 0; t2 < 16; t2++) {
            float scl = __expf(Rm[row * 16 + t2] - mm);
            zz = fmaf(Rz[row * 16 + t2], scl, zz);
            ss = fmaf(Rs[row * 16 + t2], scl, ss);
        }
        H = mm + __logf(zz) - ss / zz;   // entropy contribution (sign folded in fin)
        idxRow[row] = ii;
        idxout[r0 + row] = (float)ii;
        atomicAdd(&g_hist[ii], 1);
    }
    scr[tid] = (tid < 128) ? H : 0.f;
    __syncthreads();
    for (int s = 128; s > 0; s >>= 1) {
        if (tid < s) scr[tid] += scr[tid + s];
        __syncthreads();
    }
    if (tid == 0) g_pent[blockIdx.x] = scr[0];
    __syncthreads();

    // gather quantized rows, write output, accumulate commitment
    float ca = 0.f;
#pragma unroll
    for (int i = 0; i < 8; i++) {
        int v = tid + 256 * i;
        int row = v >> 4;
        int c4 = v & 15;
        int code = idxRow[row];
        float4 q = ((const float4*)emb)[(size_t)code * 16 + c4];
        float4 xv = ((const float4*)x)[(size_t)(r0 + row) * 16 + c4];
        ((float4*)qout)[(size_t)(r0 + row) * 16 + c4] = q;
        float dx = q.x - xv.x, dy = q.y - xv.y, dz = q.z - xv.z, dw = q.w - xv.w;
        ca += dx * dx + dy * dy + dz * dz + dw * dw;
    }
    scr[tid] = ca;
    __syncthreads();
    for (int s = 128; s > 0; s >>= 1) {
        if (tid < s) scr[tid] += scr[tid + s];
        __syncthreads();
    }
    if (tid == 0) g_pcommit[blockIdx.x] = scr[0];
}

// -------- finalize scalars --------
__global__ void fin_kernel(float* __restrict__ out, int N, int nblocks) {
    __shared__ float sh[256];
    int tid = threadIdx.x;

    float v = 0.f;
    for (int i = tid; i < nblocks; i += 256) v += g_pcommit[i];
    sh[tid] = v;
    __syncthreads();
    for (int s = 128; s > 0; s >>= 1) { if (tid < s) sh[tid] += sh[tid + s]; __syncthreads(); }
    float commitSum = sh[0];
    __syncthreads();

    v = 0.f;
    for (int i = tid; i < nblocks; i += 256) v += g_pent[i];
    sh[tid] = v;
    __syncthreads();
    for (int s = 128; s > 0; s >>= 1) { if (tid < s) sh[tid] += sh[tid + s]; __syncthreads(); }
    float entSum = sh[0];
    __syncthreads();

    // ortho: sum over 4096 Gram entries of (sum of 16 partials)^2
    v = 0.f;
    for (int e = tid; e < 4096; e += 256) {
        float s2 = 0.f;
#pragma unroll
        for (int p = 0; p < 16; p++) s2 += g_gramp[p * 4096 + e];
        v = fmaf(s2, s2, v);
    }
    sh[tid] = v;
    __syncthreads();
    for (int s = 128; s > 0; s >>= 1) { if (tid < s) sh[tid] += sh[tid + s]; __syncthreads(); }
    float orthoSum = sh[0];
    __syncthreads();

    v = 0.f;
    for (int i = tid; i < KCODES; i += 256) {
        float avg = (float)g_hist[i] / (float)N;
        v += avg * logf(avg + 1e-10f);
    }
    sh[tid] = v;
    __syncthreads();
    for (int s = 128; s > 0; s >>= 1) { if (tid < s) sh[tid] += sh[tid + s]; __syncthreads(); }
    float psum = sh[0];

    if (tid == 0) {
        size_t Q = (size_t)N * DDIM;
        float nu = g_usedp[0] + g_usedp[1] + g_usedp[2] + g_usedp[3];
        out[Q + 0] = commitSum / (float)Q;                 // commitment_loss
        out[Q + 1] = orthoSum / (nu * nu) - 1.f / nu;      // ortho_loss
        out[Q + 2] = entSum / ((float)N * 10.f);           // entropy_loss (/log2(1024))
        out[Q + 3] = expf(-psum);                          // perplexity
        out[Q + 4] = nu / (float)KCODES;                   // coverage
    }
}

extern "C" void kernel_launch(void* const* d_in, const int* in_sizes, int n_in,
                              void* d_out, int out_size) {
    const float* x   = (const float*)d_in[0];   // [16,2048,64] fp32
    const float* emb = (const float*)d_in[1];   // [1024,64] fp32
    const float* cc  = (const float*)d_in[2];   // [1024] fp32
    int N = in_sizes[0] / DDIM;                 // 32768 rows
    int nblocks = N / 128;                      // 256

    float* out = (float*)d_out;
    float* qout = out;                                  // [N*64]
    float* idxout = out + (size_t)N * DDIM + 5;         // [N] after 5 scalars

    cudaFuncSetAttribute(main_kernel, cudaFuncAttributeMaxDynamicSharedMemorySize, SMEM_BYTES);

    prep_kernel<<<4, 256>>>(emb, cc);
    ortho_kernel<<<16, 256>>>();
    main_kernel<<<nblocks, 256, SMEM_BYTES>>>(x, emb, qout, idxout);
    fin_kernel<<<1, 256>>>(out, N, nblocks);
}